// round 1
// baseline (speedup 1.0000x reference)
#include <cuda_runtime.h>

// out[i] = sum_b sum_j x1[b,j] * x2[b,(i-j) mod 1024]
// (equivalent to reference: out[i] = sum_b sum_t x1[b,(i-t)%D]*x2[b,t])

#define BSZ 128
#define D   1024
#define DMASK 1023

// Deterministic per-b partials (no atomics). 512 KB device scratch.
__device__ float g_partial[BSZ * D];

__global__ void __launch_bounds__(256, 1)
conv_kernel(const float* __restrict__ x1, const float* __restrict__ x2) {
    __shared__ __align__(16) float s1[D];
    __shared__ __align__(16) float s2[D];

    const int b   = blockIdx.x;
    const int tid = threadIdx.x;

    // Stage both rows (4 KB each) with vec4 loads: 256 threads x 1 quad.
    const float4* x1v = reinterpret_cast<const float4*>(x1 + b * D);
    const float4* x2v = reinterpret_cast<const float4*>(x2 + b * D);
    reinterpret_cast<float4*>(s1)[tid] = x1v[tid];
    reinterpret_cast<float4*>(s2)[tid] = x2v[tid];
    __syncthreads();

    const int i0 = tid * 4;  // this thread owns outputs i0..i0+3

    float acc0 = 0.f, acc1 = 0.f, acc2 = 0.f, acc3 = 0.f;

    // Sliding window W[k] = s2[(base + k) & DMASK], base = i0 - j - 4 at the
    // start of each 4-step chunk. Quad loads are 16B-aligned and never
    // straddle the circular wrap.
    float W[8];
    {
        float4 w0 = *reinterpret_cast<const float4*>(&s2[(i0 - 4) & DMASK]);
        float4 w1 = *reinterpret_cast<const float4*>(&s2[i0]);
        W[0] = w0.x; W[1] = w0.y; W[2] = w0.z; W[3] = w0.w;
        W[4] = w1.x; W[5] = w1.y; W[6] = w1.z; W[7] = w1.w;
    }

    #pragma unroll 8
    for (int j = 0; j < D; j += 4) {
        const float4 a = *reinterpret_cast<const float4*>(&s1[j]);  // broadcast

        // step j+s uses x2[(i0 + r - j - s) & DMASK] = W[r + 4 - s]
        acc0 += a.x * W[4]; acc1 += a.x * W[5]; acc2 += a.x * W[6]; acc3 += a.x * W[7];
        acc0 += a.y * W[3]; acc1 += a.y * W[4]; acc2 += a.y * W[5]; acc3 += a.y * W[6];
        acc0 += a.z * W[2]; acc1 += a.z * W[3]; acc2 += a.z * W[4]; acc3 += a.z * W[5];
        acc0 += a.w * W[1]; acc1 += a.w * W[2]; acc2 += a.w * W[3]; acc3 += a.w * W[4];

        // Refill: next chunk's base is i0 - j - 8; load its low quad.
        const float4 nw = *reinterpret_cast<const float4*>(&s2[(i0 - j - 8) & DMASK]);
        W[4] = W[0]; W[5] = W[1]; W[6] = W[2]; W[7] = W[3];
        W[0] = nw.x; W[1] = nw.y; W[2] = nw.z; W[3] = nw.w;
    }

    *reinterpret_cast<float4*>(&g_partial[b * D + i0]) =
        make_float4(acc0, acc1, acc2, acc3);
}

__global__ void __launch_bounds__(256, 1)
reduce_kernel(float* __restrict__ out) {
    const int i = blockIdx.x * 256 + threadIdx.x;  // 4 blocks x 256 = 1024
    float s = 0.f;
    #pragma unroll 16
    for (int b = 0; b < BSZ; b++) s += g_partial[b * D + i];
    out[i] = s;
}

extern "C" void kernel_launch(void* const* d_in, const int* in_sizes, int n_in,
                              void* d_out, int out_size) {
    const float* x1  = (const float*)d_in[0];  // input1: (128, 1024) fp32
    const float* x2  = (const float*)d_in[1];  // input2: (128, 1024) fp32
    float*       out = (float*)d_out;          // (1,1,1024) fp32

    conv_kernel<<<BSZ, 256>>>(x1, x2);
    reduce_kernel<<<D / 256, 256>>>(out);
}

// round 2
// speedup vs baseline: 1.1379x; 1.1379x over previous
#include <cuda_runtime.h>

// out[i] = sum_b sum_j x1[b,j] * x2[b,(i-j) mod 1024]

#define BSZ 128
#define D   1024
#define DMASK 1023

// Deterministic per-b partials (no atomics). 512 KB device scratch.
__device__ float g_partial[BSZ * D];

__global__ void __launch_bounds__(256, 1)
conv_kernel(const float* __restrict__ x1, const float* __restrict__ x2) {
    __shared__ __align__(16) float s1[D];
    __shared__ __align__(16) float s2[D];

    const int b   = blockIdx.x;
    const int tid = threadIdx.x;

    const float4* x1v = reinterpret_cast<const float4*>(x1 + b * D);
    const float4* x2v = reinterpret_cast<const float4*>(x2 + b * D);
    reinterpret_cast<float4*>(s1)[tid] = x1v[tid];
    reinterpret_cast<float4*>(s2)[tid] = x2v[tid];
    __syncthreads();

    const int i0 = tid * 4;  // this thread owns outputs i0..i0+3

    float acc0 = 0.f, acc1 = 0.f, acc2 = 0.f, acc3 = 0.f;

    // Sliding window W[k] = s2[(base + k) & DMASK]; quad loads are 16B-aligned
    // and never straddle the circular wrap.
    float W[8];
    {
        float4 w0 = *reinterpret_cast<const float4*>(&s2[(i0 - 4) & DMASK]);
        float4 w1 = *reinterpret_cast<const float4*>(&s2[i0]);
        W[0] = w0.x; W[1] = w0.y; W[2] = w0.z; W[3] = w0.w;
        W[4] = w1.x; W[5] = w1.y; W[6] = w1.z; W[7] = w1.w;
    }

    #pragma unroll 8
    for (int j = 0; j < D; j += 4) {
        const float4 a = *reinterpret_cast<const float4*>(&s1[j]);  // broadcast

        acc0 += a.x * W[4]; acc1 += a.x * W[5]; acc2 += a.x * W[6]; acc3 += a.x * W[7];
        acc0 += a.y * W[3]; acc1 += a.y * W[4]; acc2 += a.y * W[5]; acc3 += a.y * W[6];
        acc0 += a.z * W[2]; acc1 += a.z * W[3]; acc2 += a.z * W[4]; acc3 += a.z * W[5];
        acc0 += a.w * W[1]; acc1 += a.w * W[2]; acc2 += a.w * W[3]; acc3 += a.w * W[4];

        const float4 nw = *reinterpret_cast<const float4*>(&s2[(i0 - j - 8) & DMASK]);
        W[4] = W[0]; W[5] = W[1]; W[6] = W[2]; W[7] = W[3];
        W[0] = nw.x; W[1] = nw.y; W[2] = nw.z; W[3] = nw.w;
    }

    *reinterpret_cast<float4*>(&g_partial[b * D + i0]) =
        make_float4(acc0, acc1, acc2, acc3);
}

// One warp per output: 128 CTAs x 8 warps = 1024 warps.
// Lane l sums b = l, l+32, l+64, l+96 (4 independent L2-hit loads),
// then a 5-step shfl butterfly; lane 0 stores.
__global__ void __launch_bounds__(256, 1)
reduce_kernel(float* __restrict__ out) {
    const int warp = threadIdx.x >> 5;
    const int lane = threadIdx.x & 31;
    const int i    = blockIdx.x * 8 + warp;  // output index 0..1023

    float s = g_partial[(lane      ) * D + i]
            + g_partial[(lane + 32 ) * D + i]
            + g_partial[(lane + 64 ) * D + i]
            + g_partial[(lane + 96 ) * D + i];

    #pragma unroll
    for (int m = 16; m > 0; m >>= 1)
        s += __shfl_xor_sync(0xFFFFFFFFu, s, m);

    if (lane == 0) out[i] = s;
}

extern "C" void kernel_launch(void* const* d_in, const int* in_sizes, int n_in,
                              void* d_out, int out_size) {
    const float* x1  = (const float*)d_in[0];  // input1: (128, 1024) fp32
    const float* x2  = (const float*)d_in[1];  // input2: (128, 1024) fp32
    float*       out = (float*)d_out;          // (1,1,1024) fp32

    conv_kernel<<<BSZ, 256>>>(x1, x2);
    reduce_kernel<<<BSZ, 256>>>(out);
}